// round 11
// baseline (speedup 1.0000x reference)
#include <cuda_runtime.h>

#define EMB   1024
#define NH    16
#define HD    64
#define SEQ   2048
#define BATCH 2
#define MTOT  (BATCH*SEQ)      // 4096
#define NQKV  (3*EMB)          // 3072

// Scratch (device globals: no allocation allowed in kernel_launch)
__device__ float g_q[BATCH*NH*SEQ*HD];
__device__ float g_k[BATCH*NH*SEQ*HD];
__device__ float g_v[BATCH*NH*SEQ*HD];
__device__ float g_attn[MTOT*EMB];
// Pre-converted (tf32-rounded, fp32 bit container) copies
__device__ float g_x[MTOT*EMB];
__device__ float g_wqkv[EMB*NQKV];
__device__ float g_wproj[EMB*EMB];

// ---------------------------------------------------------------------------
// TF32 helpers
// ---------------------------------------------------------------------------
__device__ __forceinline__ unsigned int f2tf32(float f) {
    unsigned int u;
    asm("cvt.rna.tf32.f32 %0, %1;" : "=r"(u) : "f"(f));
    return u;
}

__device__ __forceinline__ void mma_tf32(float c[4],
                                         const unsigned int a[4],
                                         const unsigned int b[2]) {
    asm volatile(
        "mma.sync.aligned.m16n8k8.row.col.f32.tf32.tf32.f32 "
        "{%0,%1,%2,%3}, {%4,%5,%6,%7}, {%8,%9}, {%0,%1,%2,%3};"
        : "+f"(c[0]), "+f"(c[1]), "+f"(c[2]), "+f"(c[3])
        : "r"(a[0]), "r"(a[1]), "r"(a[2]), "r"(a[3]),
          "r"(b[0]), "r"(b[1]));
}

__device__ __forceinline__ void cp_async16(void* smem_dst, const void* gsrc) {
    unsigned int d = (unsigned int)__cvta_generic_to_shared(smem_dst);
    asm volatile("cp.async.cg.shared.global [%0], [%1], 16;" :: "r"(d), "l"(gsrc));
}

// ldmatrix x4: four 8x8 b16 tiles == four 8x4 tf32 tiles
__device__ __forceinline__ void ldsm4(unsigned int r[4], const void* p) {
    unsigned int a = (unsigned int)__cvta_generic_to_shared(p);
    asm volatile("ldmatrix.sync.aligned.m8n8.x4.shared.b16 {%0,%1,%2,%3}, [%4];"
        : "=r"(r[0]), "=r"(r[1]), "=r"(r[2]), "=r"(r[3]) : "r"(a));
}

// ---------------------------------------------------------------------------
// Kernel 0: pre-convert X, Wqkv, Wproj to tf32 bits (one pass, memory-bound)
// ---------------------------------------------------------------------------
#define NX4 (MTOT*EMB/4)
#define NW4 (EMB*NQKV/4)
#define NP4 (EMB*EMB/4)

__global__ __launch_bounds__(256)
void cvt_kernel(const float* __restrict__ x, const float* __restrict__ wqkv,
                const float* __restrict__ wproj)
{
    int i = blockIdx.x * 256 + threadIdx.x;
    const float4* src; float4* dst; int j;
    if (i < NX4)            { src = (const float4*)x;     dst = (float4*)g_x;     j = i; }
    else if (i < NX4+NW4)   { src = (const float4*)wqkv;  dst = (float4*)g_wqkv;  j = i - NX4; }
    else if (i < NX4+NW4+NP4){ src = (const float4*)wproj; dst = (float4*)g_wproj; j = i - NX4 - NW4; }
    else return;
    float4 v = src[j];
    float4 o;
    o.x = __uint_as_float(f2tf32(v.x));
    o.y = __uint_as_float(f2tf32(v.y));
    o.z = __uint_as_float(f2tf32(v.z));
    o.w = __uint_as_float(f2tf32(v.w));
    dst[j] = o;
}

// GEMM tile strides (words)
#define LDA 36
#define LDB 136
#define STAGE_W (128*LDA + 32*LDB)            // 8960 words per stage
#define GEMM_SMEM (3 * STAGE_W * 4)           // 107520 B
#define NCH (EMB / 32)                        // 32 K-chunks

// ---------------------------------------------------------------------------
// Kernel 1: QKV = X @ Wqkv, TF32 mma + cp.async 3-stage + ldmatrix A-frags +
// vectorized (interleaved) B-frags. Fused RoPE; writes q(scaled),k,v tf32.
// B-frag column mapping: frag nf, mma-col j  <->  global n = n_base + 4*j + nf.
// ---------------------------------------------------------------------------
__global__ __launch_bounds__(256, 2)
void qkv_rope_kernel(const float* __restrict__ cp, const float* __restrict__ snp)
{
    extern __shared__ float smf[];

    const int tid  = threadIdx.x;
    const int lane = tid & 31;
    const int warp = tid >> 5;
    const int g = lane >> 2, c = lane & 3;
    const int m_base = (warp & 1) * 64;
    const int n_base = (warp >> 1) * 32;
    const int m0 = blockIdx.y * 128;
    const int n0 = blockIdx.x * 128;

    const int rA = ((lane >> 3) & 1) * 8 + (lane & 7);
    const int cA = (lane >> 4) * 4;

    float acc[4][4][4];
#pragma unroll
    for (int i = 0; i < 4; i++)
#pragma unroll
        for (int j = 0; j < 4; j++)
#pragma unroll
            for (int r = 0; r < 4; r++) acc[i][j][r] = 0.f;

    const int arow = tid >> 3, ac4 = (tid & 7) * 4;
    const int brow = tid >> 5, bc4 = (tid & 31) * 4;

    auto issue = [&](int ch) {
        if (ch < NCH) {
            float* stA = smf + (ch % 3) * STAGE_W;
            float* stB = stA + 128 * LDA;
            int k0 = ch * 32;
#pragma unroll
            for (int it = 0; it < 4; it++) {
                int row = arow + it * 32;
                cp_async16(&stA[row * LDA + ac4],
                           &g_x[(size_t)(m0 + row) * EMB + k0 + ac4]);
            }
#pragma unroll
            for (int it = 0; it < 4; it++) {
                int row = brow + it * 8;
                cp_async16(&stB[row * LDB + bc4],
                           &g_wqkv[(size_t)(k0 + row) * NQKV + n0 + bc4]);
            }
        }
        asm volatile("cp.async.commit_group;");
    };

    issue(0);
    issue(1);

    for (int ch = 0; ch < NCH; ch++) {
        asm volatile("cp.async.wait_group 1;");
        __syncthreads();
        issue(ch + 2);

        const float* stA = smf + (ch % 3) * STAGE_W;
        const float* stB = stA + 128 * LDA;

#pragma unroll
        for (int ks = 0; ks < 4; ks++) {
            unsigned int a[4][4], b[4][2];
#pragma unroll
            for (int mf = 0; mf < 4; mf++)
                ldsm4(a[mf], &stA[(m_base + mf * 16 + rA) * LDA + ks * 8 + cA]);
            // Interleaved B-frags: one LDS.128 covers b[0..3][0], another b[0..3][1]
            float4 u0 = *(const float4*)&stB[(ks * 8 + c) * LDB + n_base + 4 * g];
            float4 u1 = *(const float4*)&stB[(ks * 8 + c + 4) * LDB + n_base + 4 * g];
            b[0][0] = __float_as_uint(u0.x); b[0][1] = __float_as_uint(u1.x);
            b[1][0] = __float_as_uint(u0.y); b[1][1] = __float_as_uint(u1.y);
            b[2][0] = __float_as_uint(u0.z); b[2][1] = __float_as_uint(u1.z);
            b[3][0] = __float_as_uint(u0.w); b[3][1] = __float_as_uint(u1.w);
#pragma unroll
            for (int mf = 0; mf < 4; mf++)
#pragma unroll
                for (int nf = 0; nf < 4; nf++)
                    mma_tf32(acc[mf][nf], a[mf], b[nf]);
        }
    }

    // Epilogue: thread owns cols [n0+n_base+8c, +8) per row.
    // col base+nf <- acc[mf][nf][half*2]; col base+4+nf <- acc[mf][nf][half*2+1]
#pragma unroll
    for (int mf = 0; mf < 4; mf++) {
#pragma unroll
        for (int half = 0; half < 2; half++) {
            int row = m0 + m_base + mf * 16 + g + half * 8;
            int b_ = row >> 11;
            int t_ = row & (SEQ - 1);
            int colbase = n0 + n_base + 8 * c;
            float vv[8];
#pragma unroll
            for (int nf = 0; nf < 4; nf++) {
                vv[nf]     = acc[mf][nf][half * 2 + 0];
                vv[4 + nf] = acc[mf][nf][half * 2 + 1];
            }
            int seg = colbase >> 10;
            int jc  = colbase & 1023;
            int h = jc >> 6, d0 = jc & 63;      // d0 is 8-aligned
            float* dst = (seg == 0) ? g_q : (seg == 1) ? g_k : g_v;
            int idx = ((b_ * NH + h) * SEQ + t_) * HD + d0;
            if (seg < 2) {
#pragma unroll
                for (int e = 0; e < 4; e++) {
                    float cc = cp [t_ * (HD / 2) + (d0 >> 1) + e];
                    float ss = snp[t_ * (HD / 2) + (d0 >> 1) + e];
                    float x0 = vv[2 * e], x1 = vv[2 * e + 1];
                    vv[2 * e]     = x0 * cc - x1 * ss;
                    vv[2 * e + 1] = x0 * ss + x1 * cc;
                }
            }
            float sc = (seg == 0) ? 0.125f : 1.f;
            float4 o0, o1;
            o0.x = __uint_as_float(f2tf32(vv[0] * sc));
            o0.y = __uint_as_float(f2tf32(vv[1] * sc));
            o0.z = __uint_as_float(f2tf32(vv[2] * sc));
            o0.w = __uint_as_float(f2tf32(vv[3] * sc));
            o1.x = __uint_as_float(f2tf32(vv[4] * sc));
            o1.y = __uint_as_float(f2tf32(vv[5] * sc));
            o1.z = __uint_as_float(f2tf32(vv[6] * sc));
            o1.w = __uint_as_float(f2tf32(vv[7] * sc));
            *(float4*)&dst[idx]     = o0;
            *(float4*)&dst[idx + 4] = o1;
        }
    }
}

// ---------------------------------------------------------------------------
// Kernel 2: causal flash attention, Br=128 / Bc=64, 256 threads (8 warps).
// TF32 mma, cp.async double-buffered K/V, ldmatrix Q/K/P frags,
// vectorized V-frags (d-interleaved), per-warp causal skip.
// V-frag mapping: frag df (0..3), mma-col j <-> d = 4*j + df;
//                 frag df (4..7), mma-col j <-> d = 32 + 4*j + (df-4).
// ---------------------------------------------------------------------------
#define LDQ 68
#define LDK 68
#define LDV 72
#define KV_W (64*LDK + 64*LDV)                       // 8960 words per buffer
#define ATTN_SMEM ((128*LDQ + 2*KV_W) * 4)           // 106496 B

__global__ __launch_bounds__(256, 2)
void attn_kernel()
{
    extern __shared__ float smf[];
    float* sq = smf;                                  // Q, then P (aliased)

    const int qt = gridDim.x - 1 - blockIdx.x;        // big tiles first
    const int bh = blockIdx.y;
    const float* Qb = g_q + (size_t)bh * SEQ * HD;
    const float* Kb = g_k + (size_t)bh * SEQ * HD;
    const float* Vb = g_v + (size_t)bh * SEQ * HD;

    const int tid  = threadIdx.x;
    const int lane = tid & 31;
    const int warp = tid >> 5;
    const int g = lane >> 2, c = lane & 3;
    const int rw = warp * 16;
    const int rA = ((lane >> 3) & 1) * 8 + (lane & 7);
    const int cA = (lane >> 4) * 4;
    const int rB = ((lane >> 4) & 1) * 8 + (lane & 7);
    const int cB = ((lane >> 3) & 1) * 4;

    const int nkt = 2 * qt + 2;

    auto skb = [&](int b) { return smf + 128 * LDQ + b * KV_W; };
    auto svb = [&](int b) { return smf + 128 * LDQ + b * KV_W + 64 * LDK; };

    auto issue_kv = [&](int kt, int b) {
        if (kt < nkt) {
            float* dk = skb(b);
            float* dv = svb(b);
#pragma unroll
            for (int it = 0; it < 4; it++) {
                int idx = tid + it * 256;
                int row = idx >> 4, c4 = (idx & 15) * 4;
                cp_async16(&dk[row * LDK + c4], &Kb[(size_t)(kt * 64 + row) * HD + c4]);
                cp_async16(&dv[row * LDV + c4], &Vb[(size_t)(kt * 64 + row) * HD + c4]);
            }
        }
        asm volatile("cp.async.commit_group;");
    };

    // Preamble: Q (128 rows) + first K/V tile
#pragma unroll
    for (int it = 0; it < 8; it++) {
        int idx = tid + it * 256;
        int row = idx >> 4, c4 = (idx & 15) * 4;
        cp_async16(&sq[row * LDQ + c4], &Qb[(size_t)(qt * 128 + row) * HD + c4]);
    }
    issue_kv(0, 0);

    unsigned int qf[8][4];
    float oacc[8][4];
#pragma unroll
    for (int df = 0; df < 8; df++)
#pragma unroll
        for (int r = 0; r < 4; r++) oacc[df][r] = 0.f;
    float mi0 = -1e30f, mi1 = -1e30f, li0 = 0.f, li1 = 0.f;

    for (int kt = 0; kt < nkt; kt++) {
        asm volatile("cp.async.wait_group 0;");
        __syncthreads();
        if (kt == 0) {
#pragma unroll
            for (int kf = 0; kf < 8; kf++)
                ldsm4(qf[kf], &sq[(rw + rA) * LDQ + kf * 8 + cA]);
            __syncthreads();   // sq now reusable as P buffer
        }
        issue_kv(kt + 1, (kt + 1) & 1);

        // Warp-level causal skip: all 16 rows masked for this key tile?
        bool active = (kt * 64 <= qt * 128 + rw + 15);
        if (active) {
            const float* sk = skb(kt & 1);
            const float* sv = svb(kt & 1);

            // S = Q K^T
            float sacc[8][4];
#pragma unroll
            for (int nf = 0; nf < 8; nf++)
#pragma unroll
                for (int r = 0; r < 4; r++) sacc[nf][r] = 0.f;

#pragma unroll
            for (int kf = 0; kf < 8; kf++) {
                unsigned int bF[4][4];
#pragma unroll
                for (int p = 0; p < 4; p++)
                    ldsm4(bF[p], &sk[(p * 16 + rB) * LDK + kf * 8 + cB]);
#pragma unroll
                for (int nf = 0; nf < 8; nf++) {
                    unsigned int b2[2] = { bF[nf >> 1][(nf & 1) * 2],
                                           bF[nf >> 1][(nf & 1) * 2 + 1] };
                    mma_tf32(sacc[nf], qf[kf], b2);
                }
            }

            // Causal mask (global coords) when the tile straddles the diagonal
            if (kt * 64 + 63 > qt * 128 + rw) {
                int r0g = qt * 128 + rw + g, r1g = r0g + 8;
#pragma unroll
                for (int nf = 0; nf < 8; nf++) {
                    int k0g = kt * 64 + nf * 8 + 2 * c, k1g = k0g + 1;
                    if (k0g > r0g) sacc[nf][0] = -1e30f;
                    if (k1g > r0g) sacc[nf][1] = -1e30f;
                    if (k0g > r1g) sacc[nf][2] = -1e30f;
                    if (k1g > r1g) sacc[nf][3] = -1e30f;
                }
            }

            // Online softmax
            float m0 = -1e30f, m1 = -1e30f;
#pragma unroll
            for (int nf = 0; nf < 8; nf++) {
                m0 = fmaxf(m0, fmaxf(sacc[nf][0], sacc[nf][1]));
                m1 = fmaxf(m1, fmaxf(sacc[nf][2], sacc[nf][3]));
            }
            m0 = fmaxf(m0, __shfl_xor_sync(0xffffffffu, m0, 1));
            m0 = fmaxf(m0, __shfl_xor_sync(0xffffffffu, m0, 2));
            m1 = fmaxf(m1, __shfl_xor_sync(0xffffffffu, m1, 1));
            m1 = fmaxf(m1, __shfl_xor_sync(0xffffffffu, m1, 2));
            float mn0 = fmaxf(mi0, m0), mn1 = fmaxf(mi1, m1);
            float al0 = __expf(mi0 - mn0), al1 = __expf(mi1 - mn1);
            mi0 = mn0; mi1 = mn1;

            float rs0 = 0.f, rs1 = 0.f;
#pragma unroll
            for (int nf = 0; nf < 8; nf++) {
                sacc[nf][0] = __expf(sacc[nf][0] - mn0);
                sacc[nf][1] = __expf(sacc[nf][1] - mn0);
                sacc[nf][2] = __expf(sacc[nf][2] - mn1);
                sacc[nf][3] = __expf(sacc[nf][3] - mn1);
                rs0 += sacc[nf][0] + sacc[nf][1];
                rs1 += sacc[nf][2] + sacc[nf][3];
            }
            rs0 += __shfl_xor_sync(0xffffffffu, rs0, 1);
            rs0 += __shfl_xor_sync(0xffffffffu, rs0, 2);
            rs1 += __shfl_xor_sync(0xffffffffu, rs1, 1);
            rs1 += __shfl_xor_sync(0xffffffffu, rs1, 2);
            li0 = li0 * al0 + rs0;
            li1 = li1 * al1 + rs1;
#pragma unroll
            for (int df = 0; df < 8; df++) {
                oacc[df][0] *= al0; oacc[df][1] *= al0;
                oacc[df][2] *= al1; oacc[df][3] *= al1;
            }

            // P -> smem (tf32), per-warp rows rw..rw+15
#pragma unroll
            for (int nf = 0; nf < 8; nf++) {
                sq[(rw + g)     * LDQ + nf * 8 + 2 * c]     = __uint_as_float(f2tf32(sacc[nf][0]));
                sq[(rw + g)     * LDQ + nf * 8 + 2 * c + 1] = __uint_as_float(f2tf32(sacc[nf][1]));
                sq[(rw + g + 8) * LDQ + nf * 8 + 2 * c]     = __uint_as_float(f2tf32(sacc[nf][2]));
                sq[(rw + g + 8) * LDQ + nf * 8 + 2 * c + 1] = __uint_as_float(f2tf32(sacc[nf][3]));
            }
            __syncwarp();

            // O += P V  (vectorized V-frags: 4 LDS.128 per jf, 8 mma)
#pragma unroll
            for (int jf = 0; jf < 8; jf++) {
                unsigned int pa[4];
                ldsm4(pa, &sq[(rw + rA) * LDQ + jf * 8 + cA]);
                float4 u0 = *(const float4*)&sv[(jf * 8 + c)     * LDV + 4 * g];
                float4 u1 = *(const float4*)&sv[(jf * 8 + c + 4) * LDV + 4 * g];
                float4 u2 = *(const float4*)&sv[(jf * 8 + c)     * LDV + 32 + 4 * g];
                float4 u3 = *(const float4*)&sv[(jf * 8 + c + 4) * LDV + 32 + 4 * g];
                unsigned int b2[2];
                b2[0] = __float_as_uint(u0.x); b2[1] = __float_as_uint(u1.x); mma_tf32(oacc[0], pa, b2);
                b2[0] = __float_as_uint(u0.y); b2[1] = __float_as_uint(u1.y); mma_tf32(oacc[1], pa, b2);
                b2[0] = __float_as_uint(u0.z); b2[1] = __float_as_uint(u1.z); mma_tf32(oacc[2], pa, b2);
                b2[0] = __float_as_uint(u0.w); b2[1] = __float_as_uint(u1.w); mma_tf32(oacc[3], pa, b2);
                b2[0] = __float_as_uint(u2.x); b2[1] = __float_as_uint(u3.x); mma_tf32(oacc[4], pa, b2);
                b2[0] = __float_as_uint(u2.y); b2[1] = __float_as_uint(u3.y); mma_tf32(oacc[5], pa, b2);
                b2[0] = __float_as_uint(u2.z); b2[1] = __float_as_uint(u3.z); mma_tf32(oacc[6], pa, b2);
                b2[0] = __float_as_uint(u2.w); b2[1] = __float_as_uint(u3.w); mma_tf32(oacc[7], pa, b2);
            }
        }
    }

    // Epilogue. Thread owns d in [8c,8c+8) u [32+8c,32+8c+8):
    //   d=8c+df <- oacc[df][r], d=8c+4+df <- oacc[df][r+1]  (df<4)
    //   d=32+8c+(df-4) <- oacc[df][r], d=32+8c+4+(df-4) <- oacc[df][r+1]
    const int b_ = bh >> 4, h = bh & 15;
    const float inv0 = 1.f / li0, inv1 = 1.f / li1;
    const int t0 = qt * 128 + rw + g, t1 = t0 + 8;
    float* o0p = &g_attn[(size_t)(b_ * SEQ + t0) * EMB + h * HD];
    float* o1p = &g_attn[(size_t)(b_ * SEQ + t1) * EMB + h * HD];
#pragma unroll
    for (int half = 0; half < 2; half++) {
        float* op = half ? o1p : o0p;
        float inv = half ? inv1 : inv0;
        int r0 = half * 2, r1 = half * 2 + 1;
        float4 a0, a1, a2, a3;
        a0.x = __uint_as_float(f2tf32(oacc[0][r0] * inv));
        a0.y = __uint_as_float(f2tf32(oacc[1][r0] * inv));
        a0.z = __uint_as_float(f2tf32(oacc[2][r0] * inv));
        a0.w = __uint_as_float(f2tf32(oacc[3][r0] * inv));
        a1.x = __uint_as_float(f2tf32(oacc[0][r1] * inv));
        a1.y = __uint_as_float(f2tf32(oacc[1][r1] * inv));
        a1.z = __uint_as_float(f2tf32(oacc[2][r1] * inv));
        a1.w = __uint_as_float(f2tf32(oacc[3][r1] * inv));
        a2.x = __uint_as_float(f2tf32(oacc[4][r0] * inv));
        a2.y = __uint_as_float(f2tf32(oacc[5][r0] * inv));
        a2.z = __uint_as_float(f2tf32(oacc[6][r0] * inv));
        a2.w = __uint_as_float(f2tf32(oacc[7][r0] * inv));
        a3.x = __uint_as_float(f2tf32(oacc[4][r1] * inv));
        a3.y = __uint_as_float(f2tf32(oacc[5][r1] * inv));
        a3.z = __uint_as_float(f2tf32(oacc[6][r1] * inv));
        a3.w = __uint_as_float(f2tf32(oacc[7][r1] * inv));
        *(float4*)&op[8 * c]          = a0;
        *(float4*)&op[8 * c + 4]      = a1;
        *(float4*)&op[32 + 8 * c]     = a2;
        *(float4*)&op[32 + 8 * c + 4] = a3;
    }
}

// ---------------------------------------------------------------------------
// Kernel 3: out = attn @ Wproj + bproj (pre-rounded inputs, interleaved B)
// ---------------------------------------------------------------------------
__global__ __launch_bounds__(256, 2)
void proj_kernel(const float* __restrict__ bias, float* __restrict__ out)
{
    extern __shared__ float smf[];

    const int tid  = threadIdx.x;
    const int lane = tid & 31;
    const int warp = tid >> 5;
    const int g = lane >> 2, c = lane & 3;
    const int m_base = (warp & 1) * 64;
    const int n_base = (warp >> 1) * 32;
    const int m0 = blockIdx.y * 128;
    const int n0 = blockIdx.x * 128;

    const int rA = ((lane >> 3) & 1) * 8 + (lane & 7);
    const int cA = (lane >> 4) * 4;

    float acc[4][4][4];
#pragma unroll
    for (int i = 0; i < 4; i++)
#pragma unroll
        for (int j = 0; j < 4; j++)
#pragma unroll
            for (int r = 0; r < 4; r++) acc[i][j][r] = 0.f;

    const int arow = tid >> 3, ac4 = (tid & 7) * 4;
    const int brow = tid >> 5, bc4 = (tid & 31) * 4;

    auto issue = [&](int ch) {
        if (ch < NCH) {
            float* stA = smf + (ch % 3) * STAGE_W;
            float* stB = stA + 128 * LDA;
            int k0 = ch * 32;
#pragma unroll
            for (int it = 0; it < 4; it++) {
                int row = arow + it * 32;
                cp_async16(&stA[row * LDA + ac4],
                           &g_attn[(size_t)(m0 + row) * EMB + k0 + ac4]);
            }
#pragma unroll
            for (int it = 0; it < 4; it++) {
                int row = brow + it * 8;
                cp_async16(&stB[row * LDB + bc4],
                           &g_wproj[(size_t)(k0 + row) * EMB + n0 + bc4]);
            }
        }
        asm volatile("cp.async.commit_group;");
    };

    issue(0);
    issue(1);

    for (int ch = 0; ch < NCH; ch++) {
        asm volatile("cp.async.wait_group 1;");
        __syncthreads();
        issue(ch + 2);

        const float* stA = smf + (ch % 3) * STAGE_W;
        const float* stB = stA + 128 * LDA;

#pragma unroll
        for (int ks = 0; ks < 4; ks++) {
            unsigned int a[4][4], b[4][2];
#pragma unroll
            for (int mf = 0; mf < 4; mf++)
                ldsm4(a[mf], &stA[(m_base + mf * 16 + rA) * LDA + ks * 8 + cA]);
            float4 u0 = *(const float4*)&stB[(ks * 8 + c) * LDB + n_base + 4 * g];
            float4 u1 = *(const float4*)&stB[(ks * 8 + c + 4) * LDB + n_base + 4 * g];
            b[0][0] = __float_as_uint(u0.x); b[0][1] = __float_as_uint(u1.x);
            b[1][0] = __float_as_uint(u0.y); b[1][1] = __float_as_uint(u1.y);
            b[2][0] = __float_as_uint(u0.z); b[2][1] = __float_as_uint(u1.z);
            b[3][0] = __float_as_uint(u0.w); b[3][1] = __float_as_uint(u1.w);
#pragma unroll
            for (int mf = 0; mf < 4; mf++)
#pragma unroll
                for (int nf = 0; nf < 4; nf++)
                    mma_tf32(acc[mf][nf], a[mf], b[nf]);
        }
    }

    // Epilogue: thread owns cols [n0+n_base+8c, +8)
#pragma unroll
    for (int mf = 0; mf < 4; mf++) {
#pragma unroll
        for (int half = 0; half < 2; half++) {
            int row = m0 + m_base + mf * 16 + g + half * 8;
            int colbase = n0 + n_base + 8 * c;
            int r0 = half * 2, r1 = half * 2 + 1;
            float4 o0, o1;
            o0.x = acc[mf][0][r0] + bias[colbase + 0];
            o0.y = acc[mf][1][r0] + bias[colbase + 1];
            o0.z = acc[mf][2][r0] + bias[colbase + 2];
            o0.w = acc[mf][3][r0] + bias[colbase + 3];
            o1.x = acc[mf][0][r1] + bias[colbase + 4];
            o1.y = acc[mf][1][r1] + bias[colbase + 5];
            o1.z = acc[mf][2][r1] + bias[colbase + 6];
            o1.w = acc[mf][3][r1] + bias[colbase + 7];
            *(float4*)&out[(size_t)row * EMB + colbase]     = o0;
            *(float4*)&out[(size_t)row * EMB + colbase + 4] = o1;
        }
    }
}

// ---------------------------------------------------------------------------
extern "C" void kernel_launch(void* const* d_in, const int* in_sizes, int n_in,
                              void* d_out, int out_size)
{
    const float* x     = (const float*)d_in[0];
    const float* Wqkv  = (const float*)d_in[1];
    const float* Wproj = (const float*)d_in[2];
    const float* bproj = (const float*)d_in[3];
    const float* cosp  = (const float*)d_in[4];
    const float* sinp  = (const float*)d_in[5];
    float* out = (float*)d_out;

    cudaFuncSetAttribute(qkv_rope_kernel,
                         cudaFuncAttributeMaxDynamicSharedMemorySize, GEMM_SMEM);
    cudaFuncSetAttribute(attn_kernel,
                         cudaFuncAttributeMaxDynamicSharedMemorySize, ATTN_SMEM);
    cudaFuncSetAttribute(proj_kernel,
                         cudaFuncAttributeMaxDynamicSharedMemorySize, GEMM_SMEM);

    cvt_kernel<<<(NX4 + NW4 + NP4 + 255) / 256, 256>>>(x, Wqkv, Wproj);
    qkv_rope_kernel<<<dim3(NQKV / 128, MTOT / 128), 256, GEMM_SMEM>>>(cosp, sinp);
    attn_kernel<<<dim3(SEQ / 128, BATCH * NH), 256, ATTN_SMEM>>>();
    proj_kernel<<<dim3(EMB / 128, MTOT / 128), 256, GEMM_SMEM>>>(bproj, out);
}

// round 13
// speedup vs baseline: 1.0655x; 1.0655x over previous
#include <cuda_runtime.h>

#define EMB   1024
#define NH    16
#define HD    64
#define SEQ   2048
#define BATCH 2
#define MTOT  (BATCH*SEQ)      // 4096
#define NQKV  (3*EMB)          // 3072

// Scratch (device globals: no allocation allowed in kernel_launch)
__device__ float g_q[BATCH*NH*SEQ*HD];
__device__ float g_k[BATCH*NH*SEQ*HD];
__device__ float g_v[BATCH*NH*SEQ*HD];
__device__ float g_attn[MTOT*EMB];
// Pre-converted (tf32-rounded, fp32 bit container) copies
__device__ float g_x[MTOT*EMB];
__device__ float g_wqkv[EMB*NQKV];
__device__ float g_wproj[EMB*EMB];

// ---------------------------------------------------------------------------
// TF32 helpers
// ---------------------------------------------------------------------------
__device__ __forceinline__ unsigned int f2tf32(float f) {
    unsigned int u;
    asm("cvt.rna.tf32.f32 %0, %1;" : "=r"(u) : "f"(f));
    return u;
}

__device__ __forceinline__ void mma_tf32(float c[4],
                                         const unsigned int a[4],
                                         const unsigned int b[2]) {
    asm volatile(
        "mma.sync.aligned.m16n8k8.row.col.f32.tf32.tf32.f32 "
        "{%0,%1,%2,%3}, {%4,%5,%6,%7}, {%8,%9}, {%0,%1,%2,%3};"
        : "+f"(c[0]), "+f"(c[1]), "+f"(c[2]), "+f"(c[3])
        : "r"(a[0]), "r"(a[1]), "r"(a[2]), "r"(a[3]),
          "r"(b[0]), "r"(b[1]));
}

__device__ __forceinline__ void cp_async16(void* smem_dst, const void* gsrc) {
    unsigned int d = (unsigned int)__cvta_generic_to_shared(smem_dst);
    asm volatile("cp.async.cg.shared.global [%0], [%1], 16;" :: "r"(d), "l"(gsrc));
}

// ldmatrix x4: four 8x8 b16 tiles == four 8x4 tf32 tiles
__device__ __forceinline__ void ldsm4(unsigned int r[4], const void* p) {
    unsigned int a = (unsigned int)__cvta_generic_to_shared(p);
    asm volatile("ldmatrix.sync.aligned.m8n8.x4.shared.b16 {%0,%1,%2,%3}, [%4];"
        : "=r"(r[0]), "=r"(r[1]), "=r"(r[2]), "=r"(r[3]) : "r"(a));
}

// ---------------------------------------------------------------------------
// Kernel 0: pre-convert X, Wqkv, Wproj to tf32 bits (one pass, memory-bound)
// ---------------------------------------------------------------------------
#define NX4 (MTOT*EMB/4)
#define NW4 (EMB*NQKV/4)
#define NP4 (EMB*EMB/4)

__global__ __launch_bounds__(256)
void cvt_kernel(const float* __restrict__ x, const float* __restrict__ wqkv,
                const float* __restrict__ wproj)
{
    int i = blockIdx.x * 256 + threadIdx.x;
    const float4* src; float4* dst; int j;
    if (i < NX4)            { src = (const float4*)x;     dst = (float4*)g_x;     j = i; }
    else if (i < NX4+NW4)   { src = (const float4*)wqkv;  dst = (float4*)g_wqkv;  j = i - NX4; }
    else if (i < NX4+NW4+NP4){ src = (const float4*)wproj; dst = (float4*)g_wproj; j = i - NX4 - NW4; }
    else return;
    float4 v = src[j];
    float4 o;
    o.x = __uint_as_float(f2tf32(v.x));
    o.y = __uint_as_float(f2tf32(v.y));
    o.z = __uint_as_float(f2tf32(v.z));
    o.w = __uint_as_float(f2tf32(v.w));
    dst[j] = o;
}

// GEMM tile strides (words)
#define LDA 36
#define LDB 136
#define STAGE_W (128*LDA + 32*LDB)            // 8960 words per stage
#define GEMM_SMEM (3 * STAGE_W * 4)           // 107520 B
#define NCH (EMB / 32)                        // 32 K-chunks

// ---------------------------------------------------------------------------
// Kernel 1: QKV = X @ Wqkv, TF32 mma + cp.async 3-stage + ldmatrix A-frags.
// Fused RoPE; writes q (scaled), k, v tf32-rounded to [B,H,T,D].
// (round-9 proven version)
// ---------------------------------------------------------------------------
__global__ __launch_bounds__(256, 2)
void qkv_rope_kernel(const float* __restrict__ cp, const float* __restrict__ snp)
{
    extern __shared__ float smf[];

    const int tid  = threadIdx.x;
    const int lane = tid & 31;
    const int warp = tid >> 5;
    const int g = lane >> 2, c = lane & 3;
    const int m_base = (warp & 1) * 64;
    const int n_base = (warp >> 1) * 32;
    const int m0 = blockIdx.y * 128;
    const int n0 = blockIdx.x * 128;

    const int rA = ((lane >> 3) & 1) * 8 + (lane & 7);
    const int cA = (lane >> 4) * 4;

    float acc[4][4][4];
#pragma unroll
    for (int i = 0; i < 4; i++)
#pragma unroll
        for (int j = 0; j < 4; j++)
#pragma unroll
            for (int r = 0; r < 4; r++) acc[i][j][r] = 0.f;

    const int arow = tid >> 3, ac4 = (tid & 7) * 4;
    const int brow = tid >> 5, bc4 = (tid & 31) * 4;

    auto issue = [&](int ch) {
        if (ch < NCH) {
            float* stA = smf + (ch % 3) * STAGE_W;
            float* stB = stA + 128 * LDA;
            int k0 = ch * 32;
#pragma unroll
            for (int it = 0; it < 4; it++) {
                int row = arow + it * 32;
                cp_async16(&stA[row * LDA + ac4],
                           &g_x[(size_t)(m0 + row) * EMB + k0 + ac4]);
            }
#pragma unroll
            for (int it = 0; it < 4; it++) {
                int row = brow + it * 8;
                cp_async16(&stB[row * LDB + bc4],
                           &g_wqkv[(size_t)(k0 + row) * NQKV + n0 + bc4]);
            }
        }
        asm volatile("cp.async.commit_group;");
    };

    issue(0);
    issue(1);

    for (int ch = 0; ch < NCH; ch++) {
        asm volatile("cp.async.wait_group 1;");
        __syncthreads();
        issue(ch + 2);

        const float* stA = smf + (ch % 3) * STAGE_W;
        const float* stB = stA + 128 * LDA;

#pragma unroll
        for (int ks = 0; ks < 4; ks++) {
            unsigned int a[4][4], b[4][2];
#pragma unroll
            for (int mf = 0; mf < 4; mf++)
                ldsm4(a[mf], &stA[(m_base + mf * 16 + rA) * LDA + ks * 8 + cA]);
#pragma unroll
            for (int nf = 0; nf < 4; nf++) {
                const float* pb = &stB[(ks * 8 + c) * LDB + n_base + nf * 8 + g];
                b[nf][0] = __float_as_uint(pb[0]);
                b[nf][1] = __float_as_uint(pb[4 * LDB]);
            }
#pragma unroll
            for (int mf = 0; mf < 4; mf++)
#pragma unroll
                for (int nf = 0; nf < 4; nf++)
                    mma_tf32(acc[mf][nf], a[mf], b[nf]);
        }
    }

    // Epilogue: RoPE + tf32-round + scatter (q pre-scaled by 1/8)
#pragma unroll
    for (int mf = 0; mf < 4; mf++) {
#pragma unroll
        for (int half = 0; half < 2; half++) {
            int row = m0 + m_base + mf * 16 + g + half * 8;
            int b_ = row >> 11;
            int t_ = row & (SEQ - 1);
#pragma unroll
            for (int nf = 0; nf < 4; nf++) {
                int col = n0 + n_base + nf * 8 + c * 2;
                float v0 = acc[mf][nf][half * 2 + 0];
                float v1 = acc[mf][nf][half * 2 + 1];
                int seg = col >> 10;
                int jc  = col & 1023;
                int h = jc >> 6, d = jc & 63;
                float* dst = (seg == 0) ? g_q : (seg == 1) ? g_k : g_v;
                int idx = ((b_ * NH + h) * SEQ + t_) * HD + d;
                float rx, ry;
                if (seg < 2) {
                    float cc = cp [t_ * (HD / 2) + (d >> 1)];
                    float ss = snp[t_ * (HD / 2) + (d >> 1)];
                    rx = v0 * cc - v1 * ss;
                    ry = v0 * ss + v1 * cc;
                    if (seg == 0) { rx *= 0.125f; ry *= 0.125f; }
                } else {
                    rx = v0; ry = v1;
                }
                float2 o2;
                o2.x = __uint_as_float(f2tf32(rx));
                o2.y = __uint_as_float(f2tf32(ry));
                *(float2*)&dst[idx] = o2;
            }
        }
    }
}

// ---------------------------------------------------------------------------
// Kernel 2: causal flash attention, TF32 mma, Br=Bc=64, 128 threads.
// SINGLE-buffered K/V + separate P buffer -> 69KB smem -> 3 CTAs/SM.
// launch_bounds(128,3): reg cap 170 >= live frag set (~160), no spill.
// Per iter: wait+barrier, compute, barrier, issue next K/V.
// ---------------------------------------------------------------------------
#define LDQ 68
#define LDK 68
#define LDV 72
// words: Q 64*68 + P 64*68 + K 64*68 + V 64*72 = 17664
#define ATTN_SMEM ((64*LDQ + 64*LDQ + 64*LDK + 64*LDV) * 4)   // 70656 B

__global__ __launch_bounds__(128, 3)
void attn_kernel()
{
    extern __shared__ float smf[];
    float* sq = smf;                       // Q (persistent)
    float* sp = sq + 64 * LDQ;             // P
    float* sk = sp + 64 * LDQ;             // K (single buffer)
    float* sv = sk + 64 * LDK;             // V (single buffer)

    const int qt = gridDim.x - 1 - blockIdx.x;        // big tiles first
    const int bh = blockIdx.y;
    const float* Qb = g_q + (size_t)bh * SEQ * HD;
    const float* Kb = g_k + (size_t)bh * SEQ * HD;
    const float* Vb = g_v + (size_t)bh * SEQ * HD;

    const int tid  = threadIdx.x;
    const int lane = tid & 31;
    const int warp = tid >> 5;
    const int g = lane >> 2, c = lane & 3;
    const int rw = warp * 16;
    const int rA = ((lane >> 3) & 1) * 8 + (lane & 7);  // A-style ldsm rows
    const int cA = (lane >> 4) * 4;
    const int rB = ((lane >> 4) & 1) * 8 + (lane & 7);  // B-style ldsm rows
    const int cB = ((lane >> 3) & 1) * 4;

    auto issue_kv = [&](int kt) {
        if (kt <= qt) {
#pragma unroll
            for (int it = 0; it < 8; it++) {
                int idx = tid + it * 128;
                int row = idx >> 4, c4 = (idx & 15) * 4;
                cp_async16(&sk[row * LDK + c4], &Kb[(size_t)(kt * 64 + row) * HD + c4]);
                cp_async16(&sv[row * LDV + c4], &Vb[(size_t)(kt * 64 + row) * HD + c4]);
            }
        }
        asm volatile("cp.async.commit_group;");
    };

    // Preamble: Q + first K/V tile, one commit group
#pragma unroll
    for (int it = 0; it < 8; it++) {
        int idx = tid + it * 128;
        int row = idx >> 4, c4 = (idx & 15) * 4;
        cp_async16(&sq[row * LDQ + c4], &Qb[(size_t)(qt * 64 + row) * HD + c4]);
    }
    issue_kv(0);

    unsigned int qf[8][4];
    float oacc[8][4];
#pragma unroll
    for (int df = 0; df < 8; df++)
#pragma unroll
        for (int r = 0; r < 4; r++) oacc[df][r] = 0.f;
    float mi0 = -1e30f, mi1 = -1e30f, li0 = 0.f, li1 = 0.f;

    for (int kt = 0; kt <= qt; kt++) {
        asm volatile("cp.async.wait_group 0;");
        __syncthreads();
        if (kt == 0) {
#pragma unroll
            for (int kf = 0; kf < 8; kf++)
                ldsm4(qf[kf], &sq[(rw + rA) * LDQ + kf * 8 + cA]);
        }

        // S = Q K^T
        float sacc[8][4];
#pragma unroll
        for (int nf = 0; nf < 8; nf++)
#pragma unroll
            for (int r = 0; r < 4; r++) sacc[nf][r] = 0.f;

#pragma unroll
        for (int kf = 0; kf < 8; kf++) {
            unsigned int bF[4][4];
#pragma unroll
            for (int p = 0; p < 4; p++)
                ldsm4(bF[p], &sk[(p * 16 + rB) * LDK + kf * 8 + cB]);
#pragma unroll
            for (int nf = 0; nf < 8; nf++) {
                unsigned int b2[2] = { bF[nf >> 1][(nf & 1) * 2],
                                       bF[nf >> 1][(nf & 1) * 2 + 1] };
                mma_tf32(sacc[nf], qf[kf], b2);
            }
        }

        // Causal mask on diagonal tile
        if (kt == qt) {
            int r0 = rw + g, r1 = rw + g + 8;
#pragma unroll
            for (int nf = 0; nf < 8; nf++) {
                int col0 = nf * 8 + 2 * c, col1 = col0 + 1;
                if (col0 > r0) sacc[nf][0] = -1e30f;
                if (col1 > r0) sacc[nf][1] = -1e30f;
                if (col0 > r1) sacc[nf][2] = -1e30f;
                if (col1 > r1) sacc[nf][3] = -1e30f;
            }
        }

        // Online softmax
        float m0 = -1e30f, m1 = -1e30f;
#pragma unroll
        for (int nf = 0; nf < 8; nf++) {
            m0 = fmaxf(m0, fmaxf(sacc[nf][0], sacc[nf][1]));
            m1 = fmaxf(m1, fmaxf(sacc[nf][2], sacc[nf][3]));
        }
        m0 = fmaxf(m0, __shfl_xor_sync(0xffffffffu, m0, 1));
        m0 = fmaxf(m0, __shfl_xor_sync(0xffffffffu, m0, 2));
        m1 = fmaxf(m1, __shfl_xor_sync(0xffffffffu, m1, 1));
        m1 = fmaxf(m1, __shfl_xor_sync(0xffffffffu, m1, 2));
        float mn0 = fmaxf(mi0, m0), mn1 = fmaxf(mi1, m1);
        float al0 = __expf(mi0 - mn0), al1 = __expf(mi1 - mn1);
        mi0 = mn0; mi1 = mn1;

        float rs0 = 0.f, rs1 = 0.f;
#pragma unroll
        for (int nf = 0; nf < 8; nf++) {
            sacc[nf][0] = __expf(sacc[nf][0] - mn0);
            sacc[nf][1] = __expf(sacc[nf][1] - mn0);
            sacc[nf][2] = __expf(sacc[nf][2] - mn1);
            sacc[nf][3] = __expf(sacc[nf][3] - mn1);
            rs0 += sacc[nf][0] + sacc[nf][1];
            rs1 += sacc[nf][2] + sacc[nf][3];
        }
        rs0 += __shfl_xor_sync(0xffffffffu, rs0, 1);
        rs0 += __shfl_xor_sync(0xffffffffu, rs0, 2);
        rs1 += __shfl_xor_sync(0xffffffffu, rs1, 1);
        rs1 += __shfl_xor_sync(0xffffffffu, rs1, 2);
        li0 = li0 * al0 + rs0;
        li1 = li1 * al1 + rs1;
#pragma unroll
        for (int df = 0; df < 8; df++) {
            oacc[df][0] *= al0; oacc[df][1] *= al0;
            oacc[df][2] *= al1; oacc[df][3] *= al1;
        }

        // P -> smem (tf32), per-warp rows rw..rw+15
#pragma unroll
        for (int nf = 0; nf < 8; nf++) {
            sp[(rw + g)     * LDQ + nf * 8 + 2 * c]     = __uint_as_float(f2tf32(sacc[nf][0]));
            sp[(rw + g)     * LDQ + nf * 8 + 2 * c + 1] = __uint_as_float(f2tf32(sacc[nf][1]));
            sp[(rw + g + 8) * LDQ + nf * 8 + 2 * c]     = __uint_as_float(f2tf32(sacc[nf][2]));
            sp[(rw + g + 8) * LDQ + nf * 8 + 2 * c + 1] = __uint_as_float(f2tf32(sacc[nf][3]));
        }
        __syncwarp();

        // O += P V
#pragma unroll
        for (int jf = 0; jf < 8; jf++) {
            unsigned int pa[4];
            ldsm4(pa, &sp[(rw + rA) * LDQ + jf * 8 + cA]);
#pragma unroll
            for (int df = 0; df < 8; df++) {
                unsigned int b2[2];
                const float* pv = &sv[(jf * 8 + c) * LDV + df * 8 + g];
                b2[0] = __float_as_uint(pv[0]);
                b2[1] = __float_as_uint(pv[4 * LDV]);
                mma_tf32(oacc[df], pa, b2);
            }
        }

        // All warps done reading K/V -> safe to overwrite single buffers
        __syncthreads();
        issue_kv(kt + 1);
    }

    // Epilogue: normalize, tf32-round, write [B,T,C]
    const int b_ = bh >> 4, h = bh & 15;
    const float inv0 = 1.f / li0, inv1 = 1.f / li1;
    const int t0 = qt * 64 + rw + g, t1 = t0 + 8;
#pragma unroll
    for (int df = 0; df < 8; df++) {
        int col = h * HD + df * 8 + 2 * c;
        float2 o0, o1;
        o0.x = __uint_as_float(f2tf32(oacc[df][0] * inv0));
        o0.y = __uint_as_float(f2tf32(oacc[df][1] * inv0));
        o1.x = __uint_as_float(f2tf32(oacc[df][2] * inv1));
        o1.y = __uint_as_float(f2tf32(oacc[df][3] * inv1));
        *(float2*)&g_attn[(size_t)(b_ * SEQ + t0) * EMB + col] = o0;
        *(float2*)&g_attn[(size_t)(b_ * SEQ + t1) * EMB + col] = o1;
    }
}

// ---------------------------------------------------------------------------
// Kernel 3: out = attn @ Wproj + bproj (round-9 proven version)
// ---------------------------------------------------------------------------
__global__ __launch_bounds__(256, 2)
void proj_kernel(const float* __restrict__ bias, float* __restrict__ out)
{
    extern __shared__ float smf[];

    const int tid  = threadIdx.x;
    const int lane = tid & 31;
    const int warp = tid >> 5;
    const int g = lane >> 2, c = lane & 3;
    const int m_base = (warp & 1) * 64;
    const int n_base = (warp >> 1) * 32;
    const int m0 = blockIdx.y * 128;
    const int n0 = blockIdx.x * 128;

    const int rA = ((lane >> 3) & 1) * 8 + (lane & 7);
    const int cA = (lane >> 4) * 4;

    float acc[4][4][4];
#pragma unroll
    for (int i = 0; i < 4; i++)
#pragma unroll
        for (int j = 0; j < 4; j++)
#pragma unroll
            for (int r = 0; r < 4; r++) acc[i][j][r] = 0.f;

    const int arow = tid >> 3, ac4 = (tid & 7) * 4;
    const int brow = tid >> 5, bc4 = (tid & 31) * 4;

    auto issue = [&](int ch) {
        if (ch < NCH) {
            float* stA = smf + (ch % 3) * STAGE_W;
            float* stB = stA + 128 * LDA;
            int k0 = ch * 32;
#pragma unroll
            for (int it = 0; it < 4; it++) {
                int row = arow + it * 32;
                cp_async16(&stA[row * LDA + ac4],
                           &g_attn[(size_t)(m0 + row) * EMB + k0 + ac4]);
            }
#pragma unroll
            for (int it = 0; it < 4; it++) {
                int row = brow + it * 8;
                cp_async16(&stB[row * LDB + bc4],
                           &g_wproj[(size_t)(k0 + row) * EMB + n0 + bc4]);
            }
        }
        asm volatile("cp.async.commit_group;");
    };

    issue(0);
    issue(1);

    for (int ch = 0; ch < NCH; ch++) {
        asm volatile("cp.async.wait_group 1;");
        __syncthreads();
        issue(ch + 2);

        const float* stA = smf + (ch % 3) * STAGE_W;
        const float* stB = stA + 128 * LDA;

#pragma unroll
        for (int ks = 0; ks < 4; ks++) {
            unsigned int a[4][4], b[4][2];
#pragma unroll
            for (int mf = 0; mf < 4; mf++)
                ldsm4(a[mf], &stA[(m_base + mf * 16 + rA) * LDA + ks * 8 + cA]);
#pragma unroll
            for (int nf = 0; nf < 4; nf++) {
                const float* pb = &stB[(ks * 8 + c) * LDB + n_base + nf * 8 + g];
                b[nf][0] = __float_as_uint(pb[0]);
                b[nf][1] = __float_as_uint(pb[4 * LDB]);
            }
#pragma unroll
            for (int mf = 0; mf < 4; mf++)
#pragma unroll
                for (int nf = 0; nf < 4; nf++)
                    mma_tf32(acc[mf][nf], a[mf], b[nf]);
        }
    }

#pragma unroll
    for (int mf = 0; mf < 4; mf++) {
#pragma unroll
        for (int half = 0; half < 2; half++) {
            int row = m0 + m_base + mf * 16 + g + half * 8;
#pragma unroll
            for (int nf = 0; nf < 4; nf++) {
                int col = n0 + n_base + nf * 8 + c * 2;
                float2 o2;
                o2.x = acc[mf][nf][half * 2 + 0] + bias[col + 0];
                o2.y = acc[mf][nf][half * 2 + 1] + bias[col + 1];
                *(float2*)&out[(size_t)row * EMB + col] = o2;
            }
        }
    }
}

// ---------------------------------------------------------------------------
extern "C" void kernel_launch(void* const* d_in, const int* in_sizes, int n_in,
                              void* d_out, int out_size)
{
    const float* x     = (const float*)d_in[0];
    const float* Wqkv  = (const float*)d_in[1];
    const float* Wproj = (const float*)d_in[2];
    const float* bproj = (const float*)d_in[3];
    const float* cosp  = (const float*)d_in[4];
    const float* sinp  = (const float*)d_in[5];
    float* out = (float*)d_out;

    cudaFuncSetAttribute(qkv_rope_kernel,
                         cudaFuncAttributeMaxDynamicSharedMemorySize, GEMM_SMEM);
    cudaFuncSetAttribute(attn_kernel,
                         cudaFuncAttributeMaxDynamicSharedMemorySize, ATTN_SMEM);
    cudaFuncSetAttribute(proj_kernel,
                         cudaFuncAttributeMaxDynamicSharedMemorySize, GEMM_SMEM);

    cvt_kernel<<<(NX4 + NW4 + NP4 + 255) / 256, 256>>>(x, Wqkv, Wproj);
    qkv_rope_kernel<<<dim3(NQKV / 128, MTOT / 128), 256, GEMM_SMEM>>>(cosp, sinp);
    attn_kernel<<<dim3(SEQ / 64, BATCH * NH), 128, ATTN_SMEM>>>();
    proj_kernel<<<dim3(EMB / 128, MTOT / 128), 256, GEMM_SMEM>>>(bproj, out);
}

// round 14
// speedup vs baseline: 1.0681x; 1.0025x over previous
#include <cuda_runtime.h>

#define EMB   1024
#define NH    16
#define HD    64
#define SEQ   2048
#define BATCH 2
#define MTOT  (BATCH*SEQ)      // 4096
#define NQKV  (3*EMB)          // 3072

// Scratch (device globals: no allocation allowed in kernel_launch)
__device__ float g_q[BATCH*NH*SEQ*HD];
__device__ float g_k[BATCH*NH*SEQ*HD];
__device__ float g_v[BATCH*NH*SEQ*HD];
__device__ float g_attn[MTOT*EMB];
// Pre-converted (tf32-rounded, fp32 bit container) copies
__device__ float g_x[MTOT*EMB];
__device__ float g_wqkv[EMB*NQKV];
__device__ float g_wproj[EMB*EMB];

// ---------------------------------------------------------------------------
// TF32 helpers
// ---------------------------------------------------------------------------
__device__ __forceinline__ unsigned int f2tf32(float f) {
    unsigned int u;
    asm("cvt.rna.tf32.f32 %0, %1;" : "=r"(u) : "f"(f));
    return u;
}

__device__ __forceinline__ void mma_tf32(float c[4],
                                         const unsigned int a[4],
                                         const unsigned int b[2]) {
    asm volatile(
        "mma.sync.aligned.m16n8k8.row.col.f32.tf32.tf32.f32 "
        "{%0,%1,%2,%3}, {%4,%5,%6,%7}, {%8,%9}, {%0,%1,%2,%3};"
        : "+f"(c[0]), "+f"(c[1]), "+f"(c[2]), "+f"(c[3])
        : "r"(a[0]), "r"(a[1]), "r"(a[2]), "r"(a[3]),
          "r"(b[0]), "r"(b[1]));
}

__device__ __forceinline__ void cp_async16(void* smem_dst, const void* gsrc) {
    unsigned int d = (unsigned int)__cvta_generic_to_shared(smem_dst);
    asm volatile("cp.async.cg.shared.global [%0], [%1], 16;" :: "r"(d), "l"(gsrc));
}

// ldmatrix x4: four 8x8 b16 tiles == four 8x4 tf32 tiles
__device__ __forceinline__ void ldsm4(unsigned int r[4], const void* p) {
    unsigned int a = (unsigned int)__cvta_generic_to_shared(p);
    asm volatile("ldmatrix.sync.aligned.m8n8.x4.shared.b16 {%0,%1,%2,%3}, [%4];"
        : "=r"(r[0]), "=r"(r[1]), "=r"(r[2]), "=r"(r[3]) : "r"(a));
}

// ---------------------------------------------------------------------------
// Kernel 0: pre-convert X, Wqkv, Wproj to tf32 bits (one pass, memory-bound)
// ---------------------------------------------------------------------------
#define NX4 (MTOT*EMB/4)
#define NW4 (EMB*NQKV/4)
#define NP4 (EMB*EMB/4)

__global__ __launch_bounds__(256)
void cvt_kernel(const float* __restrict__ x, const float* __restrict__ wqkv,
                const float* __restrict__ wproj)
{
    int i = blockIdx.x * 256 + threadIdx.x;
    const float4* src; float4* dst; int j;
    if (i < NX4)            { src = (const float4*)x;     dst = (float4*)g_x;     j = i; }
    else if (i < NX4+NW4)   { src = (const float4*)wqkv;  dst = (float4*)g_wqkv;  j = i - NX4; }
    else if (i < NX4+NW4+NP4){ src = (const float4*)wproj; dst = (float4*)g_wproj; j = i - NX4 - NW4; }
    else return;
    float4 v = src[j];
    float4 o;
    o.x = __uint_as_float(f2tf32(v.x));
    o.y = __uint_as_float(f2tf32(v.y));
    o.z = __uint_as_float(f2tf32(v.z));
    o.w = __uint_as_float(f2tf32(v.w));
    dst[j] = o;
}

// GEMM tile strides (words)
#define LDA 36
#define LDB 136
#define STAGE_W (128*LDA + 32*LDB)            // 8960 words per stage
#define GEMM_SMEM (3 * STAGE_W * 4)           // 107520 B
#define NCH (EMB / 32)                        // 32 K-chunks

// ---------------------------------------------------------------------------
// Kernel 1: QKV = X @ Wqkv (round-9 proven version)
// ---------------------------------------------------------------------------
__global__ __launch_bounds__(256, 2)
void qkv_rope_kernel(const float* __restrict__ cp, const float* __restrict__ snp)
{
    extern __shared__ float smf[];

    const int tid  = threadIdx.x;
    const int lane = tid & 31;
    const int warp = tid >> 5;
    const int g = lane >> 2, c = lane & 3;
    const int m_base = (warp & 1) * 64;
    const int n_base = (warp >> 1) * 32;
    const int m0 = blockIdx.y * 128;
    const int n0 = blockIdx.x * 128;

    const int rA = ((lane >> 3) & 1) * 8 + (lane & 7);
    const int cA = (lane >> 4) * 4;

    float acc[4][4][4];
#pragma unroll
    for (int i = 0; i < 4; i++)
#pragma unroll
        for (int j = 0; j < 4; j++)
#pragma unroll
            for (int r = 0; r < 4; r++) acc[i][j][r] = 0.f;

    const int arow = tid >> 3, ac4 = (tid & 7) * 4;
    const int brow = tid >> 5, bc4 = (tid & 31) * 4;

    auto issue = [&](int ch) {
        if (ch < NCH) {
            float* stA = smf + (ch % 3) * STAGE_W;
            float* stB = stA + 128 * LDA;
            int k0 = ch * 32;
#pragma unroll
            for (int it = 0; it < 4; it++) {
                int row = arow + it * 32;
                cp_async16(&stA[row * LDA + ac4],
                           &g_x[(size_t)(m0 + row) * EMB + k0 + ac4]);
            }
#pragma unroll
            for (int it = 0; it < 4; it++) {
                int row = brow + it * 8;
                cp_async16(&stB[row * LDB + bc4],
                           &g_wqkv[(size_t)(k0 + row) * NQKV + n0 + bc4]);
            }
        }
        asm volatile("cp.async.commit_group;");
    };

    issue(0);
    issue(1);

    for (int ch = 0; ch < NCH; ch++) {
        asm volatile("cp.async.wait_group 1;");
        __syncthreads();
        issue(ch + 2);

        const float* stA = smf + (ch % 3) * STAGE_W;
        const float* stB = stA + 128 * LDA;

#pragma unroll
        for (int ks = 0; ks < 4; ks++) {
            unsigned int a[4][4], b[4][2];
#pragma unroll
            for (int mf = 0; mf < 4; mf++)
                ldsm4(a[mf], &stA[(m_base + mf * 16 + rA) * LDA + ks * 8 + cA]);
#pragma unroll
            for (int nf = 0; nf < 4; nf++) {
                const float* pb = &stB[(ks * 8 + c) * LDB + n_base + nf * 8 + g];
                b[nf][0] = __float_as_uint(pb[0]);
                b[nf][1] = __float_as_uint(pb[4 * LDB]);
            }
#pragma unroll
            for (int mf = 0; mf < 4; mf++)
#pragma unroll
                for (int nf = 0; nf < 4; nf++)
                    mma_tf32(acc[mf][nf], a[mf], b[nf]);
        }
    }

    // Epilogue: RoPE + tf32-round + scatter (q pre-scaled by 1/8)
#pragma unroll
    for (int mf = 0; mf < 4; mf++) {
#pragma unroll
        for (int half = 0; half < 2; half++) {
            int row = m0 + m_base + mf * 16 + g + half * 8;
            int b_ = row >> 11;
            int t_ = row & (SEQ - 1);
#pragma unroll
            for (int nf = 0; nf < 4; nf++) {
                int col = n0 + n_base + nf * 8 + c * 2;
                float v0 = acc[mf][nf][half * 2 + 0];
                float v1 = acc[mf][nf][half * 2 + 1];
                int seg = col >> 10;
                int jc  = col & 1023;
                int h = jc >> 6, d = jc & 63;
                float* dst = (seg == 0) ? g_q : (seg == 1) ? g_k : g_v;
                int idx = ((b_ * NH + h) * SEQ + t_) * HD + d;
                float rx, ry;
                if (seg < 2) {
                    float cc = cp [t_ * (HD / 2) + (d >> 1)];
                    float ss = snp[t_ * (HD / 2) + (d >> 1)];
                    rx = v0 * cc - v1 * ss;
                    ry = v0 * ss + v1 * cc;
                    if (seg == 0) { rx *= 0.125f; ry *= 0.125f; }
                } else {
                    rx = v0; ry = v1;
                }
                float2 o2;
                o2.x = __uint_as_float(f2tf32(rx));
                o2.y = __uint_as_float(f2tf32(ry));
                *(float2*)&dst[idx] = o2;
            }
        }
    }
}

// ---------------------------------------------------------------------------
// Kernel 2: causal flash attention — round-9 structure (Br=Bc=64, 128 thr,
// double-buffered K/V cp.async, ldsm Q/K/P) + vectorized d-interleaved V
// fragments (128 scalar LDS -> 32 LDS.128 per iter) + float2 P-stores.
// V-frag mapping: frag df(0..3): d = 4*j + df; df(4..7): d = 32 + 4*j + (df-4).
// ---------------------------------------------------------------------------
#define LDQ 68
#define LDK 68
#define LDV 72
#define KV_W (64*LDK + 64*LDV)                       // 8960 words per buffer
#define ATTN_SMEM ((64*LDQ + 2*KV_W) * 4)            // 89088 B

__global__ __launch_bounds__(128)
void attn_kernel()
{
    extern __shared__ float smf[];
    float* sq = smf;                                  // Q, then P (aliased)

    const int qt = gridDim.x - 1 - blockIdx.x;        // big tiles first
    const int bh = blockIdx.y;
    const float* Qb = g_q + (size_t)bh * SEQ * HD;
    const float* Kb = g_k + (size_t)bh * SEQ * HD;
    const float* Vb = g_v + (size_t)bh * SEQ * HD;

    const int tid  = threadIdx.x;
    const int lane = tid & 31;
    const int warp = tid >> 5;
    const int g = lane >> 2, c = lane & 3;
    const int rw = warp * 16;
    const int rA = ((lane >> 3) & 1) * 8 + (lane & 7);  // A-style ldsm rows
    const int cA = (lane >> 4) * 4;
    const int rB = ((lane >> 4) & 1) * 8 + (lane & 7);  // B-style ldsm rows
    const int cB = ((lane >> 3) & 1) * 4;

    auto skb = [&](int b) { return smf + 64 * LDQ + b * KV_W; };
    auto svb = [&](int b) { return smf + 64 * LDQ + b * KV_W + 64 * LDK; };

    auto issue_kv = [&](int kt, int b) {
        if (kt <= qt) {
            float* dk = skb(b);
            float* dv = svb(b);
#pragma unroll
            for (int it = 0; it < 8; it++) {
                int idx = tid + it * 128;
                int row = idx >> 4, c4 = (idx & 15) * 4;
                cp_async16(&dk[row * LDK + c4], &Kb[(size_t)(kt * 64 + row) * HD + c4]);
                cp_async16(&dv[row * LDV + c4], &Vb[(size_t)(kt * 64 + row) * HD + c4]);
            }
        }
        asm volatile("cp.async.commit_group;");
    };

    // Preamble: Q + first K/V tile, one group
#pragma unroll
    for (int it = 0; it < 8; it++) {
        int idx = tid + it * 128;
        int row = idx >> 4, c4 = (idx & 15) * 4;
        cp_async16(&sq[row * LDQ + c4], &Qb[(size_t)(qt * 64 + row) * HD + c4]);
    }
    issue_kv(0, 0);

    unsigned int qf[8][4];
    float oacc[8][4];
#pragma unroll
    for (int df = 0; df < 8; df++)
#pragma unroll
        for (int r = 0; r < 4; r++) oacc[df][r] = 0.f;
    float mi0 = -1e30f, mi1 = -1e30f, li0 = 0.f, li1 = 0.f;

    for (int kt = 0; kt <= qt; kt++) {
        asm volatile("cp.async.wait_group 0;");
        __syncthreads();
        if (kt == 0) {
#pragma unroll
            for (int kf = 0; kf < 8; kf++)
                ldsm4(qf[kf], &sq[(rw + rA) * LDQ + kf * 8 + cA]);
            __syncthreads();   // sq now reusable as P buffer
        }
        issue_kv(kt + 1, (kt + 1) & 1);

        const float* sk = skb(kt & 1);
        const float* sv = svb(kt & 1);

        // S = Q K^T
        float sacc[8][4];
#pragma unroll
        for (int nf = 0; nf < 8; nf++)
#pragma unroll
            for (int r = 0; r < 4; r++) sacc[nf][r] = 0.f;

#pragma unroll
        for (int kf = 0; kf < 8; kf++) {
            unsigned int bF[4][4];
#pragma unroll
            for (int p = 0; p < 4; p++)
                ldsm4(bF[p], &sk[(p * 16 + rB) * LDK + kf * 8 + cB]);
#pragma unroll
            for (int nf = 0; nf < 8; nf++) {
                unsigned int b2[2] = { bF[nf >> 1][(nf & 1) * 2],
                                       bF[nf >> 1][(nf & 1) * 2 + 1] };
                mma_tf32(sacc[nf], qf[kf], b2);
            }
        }

        // Causal mask on diagonal tile
        if (kt == qt) {
            int r0 = rw + g, r1 = rw + g + 8;
#pragma unroll
            for (int nf = 0; nf < 8; nf++) {
                int col0 = nf * 8 + 2 * c, col1 = col0 + 1;
                if (col0 > r0) sacc[nf][0] = -1e30f;
                if (col1 > r0) sacc[nf][1] = -1e30f;
                if (col0 > r1) sacc[nf][2] = -1e30f;
                if (col1 > r1) sacc[nf][3] = -1e30f;
            }
        }

        // Online softmax
        float m0 = -1e30f, m1 = -1e30f;
#pragma unroll
        for (int nf = 0; nf < 8; nf++) {
            m0 = fmaxf(m0, fmaxf(sacc[nf][0], sacc[nf][1]));
            m1 = fmaxf(m1, fmaxf(sacc[nf][2], sacc[nf][3]));
        }
        m0 = fmaxf(m0, __shfl_xor_sync(0xffffffffu, m0, 1));
        m0 = fmaxf(m0, __shfl_xor_sync(0xffffffffu, m0, 2));
        m1 = fmaxf(m1, __shfl_xor_sync(0xffffffffu, m1, 1));
        m1 = fmaxf(m1, __shfl_xor_sync(0xffffffffu, m1, 2));
        float mn0 = fmaxf(mi0, m0), mn1 = fmaxf(mi1, m1);
        float al0 = __expf(mi0 - mn0), al1 = __expf(mi1 - mn1);
        mi0 = mn0; mi1 = mn1;

        float rs0 = 0.f, rs1 = 0.f;
#pragma unroll
        for (int nf = 0; nf < 8; nf++) {
            sacc[nf][0] = __expf(sacc[nf][0] - mn0);
            sacc[nf][1] = __expf(sacc[nf][1] - mn0);
            sacc[nf][2] = __expf(sacc[nf][2] - mn1);
            sacc[nf][3] = __expf(sacc[nf][3] - mn1);
            rs0 += sacc[nf][0] + sacc[nf][1];
            rs1 += sacc[nf][2] + sacc[nf][3];
        }
        rs0 += __shfl_xor_sync(0xffffffffu, rs0, 1);
        rs0 += __shfl_xor_sync(0xffffffffu, rs0, 2);
        rs1 += __shfl_xor_sync(0xffffffffu, rs1, 1);
        rs1 += __shfl_xor_sync(0xffffffffu, rs1, 2);
        li0 = li0 * al0 + rs0;
        li1 = li1 * al1 + rs1;
#pragma unroll
        for (int df = 0; df < 8; df++) {
            oacc[df][0] *= al0; oacc[df][1] *= al0;
            oacc[df][2] *= al1; oacc[df][3] *= al1;
        }

        // P -> smem (tf32), float2 stores, per-warp rows rw..rw+15
#pragma unroll
        for (int nf = 0; nf < 8; nf++) {
            float2 p0, p1;
            p0.x = __uint_as_float(f2tf32(sacc[nf][0]));
            p0.y = __uint_as_float(f2tf32(sacc[nf][1]));
            p1.x = __uint_as_float(f2tf32(sacc[nf][2]));
            p1.y = __uint_as_float(f2tf32(sacc[nf][3]));
            *(float2*)&sq[(rw + g)     * LDQ + nf * 8 + 2 * c] = p0;
            *(float2*)&sq[(rw + g + 8) * LDQ + nf * 8 + 2 * c] = p1;
        }
        __syncwarp();

        // O += P V  (vectorized d-interleaved V frags: 4 LDS.128 per jf)
#pragma unroll
        for (int jf = 0; jf < 8; jf++) {
            unsigned int pa[4];
            ldsm4(pa, &sq[(rw + rA) * LDQ + jf * 8 + cA]);
            float4 u0 = *(const float4*)&sv[(jf * 8 + c)     * LDV + 4 * g];
            float4 u1 = *(const float4*)&sv[(jf * 8 + c + 4) * LDV + 4 * g];
            float4 u2 = *(const float4*)&sv[(jf * 8 + c)     * LDV + 32 + 4 * g];
            float4 u3 = *(const float4*)&sv[(jf * 8 + c + 4) * LDV + 32 + 4 * g];
            unsigned int b2[2];
            b2[0] = __float_as_uint(u0.x); b2[1] = __float_as_uint(u1.x); mma_tf32(oacc[0], pa, b2);
            b2[0] = __float_as_uint(u0.y); b2[1] = __float_as_uint(u1.y); mma_tf32(oacc[1], pa, b2);
            b2[0] = __float_as_uint(u0.z); b2[1] = __float_as_uint(u1.z); mma_tf32(oacc[2], pa, b2);
            b2[0] = __float_as_uint(u0.w); b2[1] = __float_as_uint(u1.w); mma_tf32(oacc[3], pa, b2);
            b2[0] = __float_as_uint(u2.x); b2[1] = __float_as_uint(u3.x); mma_tf32(oacc[4], pa, b2);
            b2[0] = __float_as_uint(u2.y); b2[1] = __float_as_uint(u3.y); mma_tf32(oacc[5], pa, b2);
            b2[0] = __float_as_uint(u2.z); b2[1] = __float_as_uint(u3.z); mma_tf32(oacc[6], pa, b2);
            b2[0] = __float_as_uint(u2.w); b2[1] = __float_as_uint(u3.w); mma_tf32(oacc[7], pa, b2);
        }
    }

    // Epilogue (interleaved d mapping). Thread owns
    // d = 8c+df, 8c+4+df (df<4) and 32+8c+(df-4), 32+8c+4+(df-4) (df>=4),
    // rows t0 (regs 0,1) and t1 (regs 2,3).
    const int b_ = bh >> 4, h = bh & 15;
    const float inv0 = 1.f / li0, inv1 = 1.f / li1;
    const int t0 = qt * 64 + rw + g, t1 = t0 + 8;
    float* o0p = &g_attn[(size_t)(b_ * SEQ + t0) * EMB + h * HD];
    float* o1p = &g_attn[(size_t)(b_ * SEQ + t1) * EMB + h * HD];
#pragma unroll
    for (int half = 0; half < 2; half++) {
        float* op = half ? o1p : o0p;
        float inv = half ? inv1 : inv0;
        int r0 = half * 2, r1 = half * 2 + 1;
        float4 a0, a1, a2, a3;
        a0.x = __uint_as_float(f2tf32(oacc[0][r0] * inv));
        a0.y = __uint_as_float(f2tf32(oacc[1][r0] * inv));
        a0.z = __uint_as_float(f2tf32(oacc[2][r0] * inv));
        a0.w = __uint_as_float(f2tf32(oacc[3][r0] * inv));
        a1.x = __uint_as_float(f2tf32(oacc[0][r1] * inv));
        a1.y = __uint_as_float(f2tf32(oacc[1][r1] * inv));
        a1.z = __uint_as_float(f2tf32(oacc[2][r1] * inv));
        a1.w = __uint_as_float(f2tf32(oacc[3][r1] * inv));
        a2.x = __uint_as_float(f2tf32(oacc[4][r0] * inv));
        a2.y = __uint_as_float(f2tf32(oacc[5][r0] * inv));
        a2.z = __uint_as_float(f2tf32(oacc[6][r0] * inv));
        a2.w = __uint_as_float(f2tf32(oacc[7][r0] * inv));
        a3.x = __uint_as_float(f2tf32(oacc[4][r1] * inv));
        a3.y = __uint_as_float(f2tf32(oacc[5][r1] * inv));
        a3.z = __uint_as_float(f2tf32(oacc[6][r1] * inv));
        a3.w = __uint_as_float(f2tf32(oacc[7][r1] * inv));
        *(float4*)&op[8 * c]          = a0;
        *(float4*)&op[8 * c + 4]      = a1;
        *(float4*)&op[32 + 8 * c]     = a2;
        *(float4*)&op[32 + 8 * c + 4] = a3;
    }
}

// ---------------------------------------------------------------------------
// Kernel 3: out = attn @ Wproj + bproj (round-9 proven version)
// ---------------------------------------------------------------------------
__global__ __launch_bounds__(256, 2)
void proj_kernel(const float* __restrict__ bias, float* __restrict__ out)
{
    extern __shared__ float smf[];

    const int tid  = threadIdx.x;
    const int lane = tid & 31;
    const int warp = tid >> 5;
    const int g = lane >> 2, c = lane & 3;
    const int m_base = (warp & 1) * 64;
    const int n_base = (warp >> 1) * 32;
    const int m0 = blockIdx.y * 128;
    const int n0 = blockIdx.x * 128;

    const int rA = ((lane >> 3) & 1) * 8 + (lane & 7);
    const int cA = (lane >> 4) * 4;

    float acc[4][4][4];
#pragma unroll
    for (int i = 0; i < 4; i++)
#pragma unroll
        for (int j = 0; j < 4; j++)
#pragma unroll
            for (int r = 0; r < 4; r++) acc[i][j][r] = 0.f;

    const int arow = tid >> 3, ac4 = (tid & 7) * 4;
    const int brow = tid >> 5, bc4 = (tid & 31) * 4;

    auto issue = [&](int ch) {
        if (ch < NCH) {
            float* stA = smf + (ch % 3) * STAGE_W;
            float* stB = stA + 128 * LDA;
            int k0 = ch * 32;
#pragma unroll
            for (int it = 0; it < 4; it++) {
                int row = arow + it * 32;
                cp_async16(&stA[row * LDA + ac4],
                           &g_attn[(size_t)(m0 + row) * EMB + k0 + ac4]);
            }
#pragma unroll
            for (int it = 0; it < 4; it++) {
                int row = brow + it * 8;
                cp_async16(&stB[row * LDB + bc4],
                           &g_wproj[(size_t)(k0 + row) * EMB + n0 + bc4]);
            }
        }
        asm volatile("cp.async.commit_group;");
    };

    issue(0);
    issue(1);

    for (int ch = 0; ch < NCH; ch++) {
        asm volatile("cp.async.wait_group 1;");
        __syncthreads();
        issue(ch + 2);

        const float* stA = smf + (ch % 3) * STAGE_W;
        const float* stB = stA + 128 * LDA;

#pragma unroll
        for (int ks = 0; ks < 4; ks++) {
            unsigned int a[4][4], b[4][2];
#pragma unroll
            for (int mf = 0; mf < 4; mf++)
                ldsm4(a[mf], &stA[(m_base + mf * 16 + rA) * LDA + ks * 8 + cA]);
#pragma unroll
            for (int nf = 0; nf < 4; nf++) {
                const float* pb = &stB[(ks * 8 + c) * LDB + n_base + nf * 8 + g];
                b[nf][0] = __float_as_uint(pb[0]);
                b[nf][1] = __float_as_uint(pb[4 * LDB]);
            }
#pragma unroll
            for (int mf = 0; mf < 4; mf++)
#pragma unroll
                for (int nf = 0; nf < 4; nf++)
                    mma_tf32(acc[mf][nf], a[mf], b[nf]);
        }
    }

#pragma unroll
    for (int mf = 0; mf < 4; mf++) {
#pragma unroll
        for (int half = 0; half < 2; half++) {
            int row = m0 + m_base + mf * 16 + g + half * 8;
#pragma unroll
            for (int nf = 0; nf < 4; nf++) {
                int col = n0 + n_base + nf * 8 + c * 2;
                float2 o2;
                o2.x = acc[mf][nf][half * 2 + 0] + bias[col + 0];
                o2.y = acc[mf][nf][half * 2 + 1] + bias[col + 1];
                *(float2*)&out[(size_t)row * EMB + col] = o2;
            }
        }
    }
}

// ---------------------------------------------------------------------------
extern "C" void kernel_launch(void* const* d_in, const int* in_sizes, int n_in,
                              void* d_out, int out_size)
{
    const float* x     = (const float*)d_in[0];
    const float* Wqkv  = (const float*)d_in[1];
    const float* Wproj = (const float*)d_in[2];
    const float* bproj = (const float*)d_in[3];
    const float* cosp  = (const float*)d_in[4];
    const float* sinp  = (const float*)d_in[5];
    float* out = (float*)d_out;

    cudaFuncSetAttribute(qkv_rope_kernel,
                         cudaFuncAttributeMaxDynamicSharedMemorySize, GEMM_SMEM);
    cudaFuncSetAttribute(attn_kernel,
                         cudaFuncAttributeMaxDynamicSharedMemorySize, ATTN_SMEM);
    cudaFuncSetAttribute(proj_kernel,
                         cudaFuncAttributeMaxDynamicSharedMemorySize, GEMM_SMEM);

    cvt_kernel<<<(NX4 + NW4 + NP4 + 255) / 256, 256>>>(x, Wqkv, Wproj);
    qkv_rope_kernel<<<dim3(NQKV / 128, MTOT / 128), 256, GEMM_SMEM>>>(cosp, sinp);
    attn_kernel<<<dim3(SEQ / 64, BATCH * NH), 128, ATTN_SMEM>>>();
    proj_kernel<<<dim3(EMB / 128, MTOT / 128), 256, GEMM_SMEM>>>(bproj, out);
}